// round 12
// baseline (speedup 1.0000x reference)
#include <cuda_runtime.h>
#include <cuda_bf16.h>
#include <math.h>

// Problem constants
#define B_    32
#define S_    512
#define DIN_  512
#define DH_   1024
#define DOUT_ 512
#define NG_   4096   // 4 * DH_
#define M_    (B_ * S_)   // 16384

#define NCTA_  128

// ---- persistent mma kernel smem layout (bytes) ----
#define ROWB      2064                  // h plane row stride: 1024*2 + 16 pad
#define HPLANE_B  (32 * ROWB)           // 66048
#define ZP_OFF    (2 * HPLANE_B)        // 132096
#define ZP_STRIDE 34                    // floats per zp row
#define ZP_B      (4 * 32 * ZP_STRIDE * 4)   // 17408
#define CS_OFF    (ZP_OFF + ZP_B)       // 149504
#define SMEM_P_BYTES (CS_OFF + 256 * 4) // 150528

// -------- scratch (device globals; no allocation allowed) --------
__device__ float g_gatesx[S_ * B_ * NG_];        // [m=t*32+b][4096], n = gate*1024+j
__device__ __nv_bfloat16 g_xhi[M_ * DIN_];       // A planes for gatesx: [m][512]
__device__ __nv_bfloat16 g_xlo[M_ * DIN_];
__device__ __nv_bfloat16 g_whx[DIN_ * NG_];      // B planes: [k][4096]
__device__ __nv_bfloat16 g_wlx[DIN_ * NG_];
__device__ float g_ball[NG_];                    // combined bias
__device__ __nv_bfloat16 g_fchi[DH_ * DOUT_];    // [k][512]
__device__ __nv_bfloat16 g_fclo[DH_ * DOUT_];
__device__ __nv_bfloat16 g_hshi[S_ * B_ * DH_];  // hs planes: [t][b][1024]
__device__ __nv_bfloat16 g_hslo[S_ * B_ * DH_];
__device__ __nv_bfloat16 g_h0hi[B_ * DH_];       // zero h for t=0
__device__ __nv_bfloat16 g_h0lo[B_ * DH_];
__device__ unsigned g_bar;

// ---------------- helpers ----------------
__device__ __forceinline__ float sigf(float x) {
    return __fdividef(1.0f, 1.0f + __expf(-x));
}
__device__ __forceinline__ float tanhfast(float x) {
    return __fdividef(2.0f, 1.0f + __expf(-2.0f * x)) - 1.0f;
}
__device__ __forceinline__ unsigned s2u(const void* p) {
    return (unsigned)__cvta_generic_to_shared(p);
}
__device__ __forceinline__ void split2(float a, float b, unsigned& hi, unsigned& lo) {
    __nv_bfloat16 ah = __float2bfloat16(a);
    __nv_bfloat16 bh = __float2bfloat16(b);
    float ar = a - __bfloat162float(ah);
    float br = b - __bfloat162float(bh);
    __nv_bfloat162 hv; hv.x = ah; hv.y = bh;
    __nv_bfloat162 lv; lv.x = __float2bfloat16(ar); lv.y = __float2bfloat16(br);
    hi = *reinterpret_cast<unsigned*>(&hv);
    lo = *reinterpret_cast<unsigned*>(&lv);
}
__device__ __forceinline__ void ldsm4(unsigned& r0, unsigned& r1, unsigned& r2,
                                      unsigned& r3, unsigned addr) {
    asm volatile("ldmatrix.sync.aligned.m8n8.x4.shared.b16 {%0,%1,%2,%3}, [%4];"
                 : "=r"(r0), "=r"(r1), "=r"(r2), "=r"(r3) : "r"(addr));
}
__device__ __forceinline__ void ldsm4t(unsigned& r0, unsigned& r1, unsigned& r2,
                                       unsigned& r3, unsigned addr) {
    asm volatile("ldmatrix.sync.aligned.m8n8.x4.trans.shared.b16 {%0,%1,%2,%3}, [%4];"
                 : "=r"(r0), "=r"(r1), "=r"(r2), "=r"(r3) : "r"(addr));
}
__device__ __forceinline__ void mma_bf16(float& c0, float& c1, float& c2, float& c3,
                                         unsigned a0, unsigned a1, unsigned a2, unsigned a3,
                                         unsigned b0, unsigned b1) {
    asm volatile("mma.sync.aligned.m16n8k16.row.col.f32.bf16.bf16.f32 "
                 "{%0,%1,%2,%3},{%4,%5,%6,%7},{%8,%9},{%0,%1,%2,%3};"
                 : "+f"(c0), "+f"(c1), "+f"(c2), "+f"(c3)
                 : "r"(a0), "r"(a1), "r"(a2), "r"(a3), "r"(b0), "r"(b1));
}
__device__ __forceinline__ void cpasync16(unsigned dst, const void* src) {
    asm volatile("cp.async.cg.shared.global [%0], [%1], 16;" :: "r"(dst), "l"(src));
}
__device__ __forceinline__ void cp_commit() {
    asm volatile("cp.async.commit_group;" ::: "memory");
}
template <int N>
__device__ __forceinline__ void cp_wait() {
    asm volatile("cp.async.wait_group %0;" :: "n"(N) : "memory");
}

// ----------------------------------------------------------------
__global__ void init_state_kernel() {
    int i = blockIdx.x * blockDim.x + threadIdx.x;
    if (i < B_ * DH_) {
        g_h0hi[i] = __float2bfloat16(0.0f);
        g_h0lo[i] = __float2bfloat16(0.0f);
    }
    if (i == 0) g_bar = 0u;
}

// ----------------------------------------------------------------
// Convert kernels: fp32 -> bf16 hi/lo planes
// ----------------------------------------------------------------
__global__ void conv_w_kernel(const float* __restrict__ Wf, const float* __restrict__ Wi,
                              const float* __restrict__ Wg, const float* __restrict__ Wo,
                              const float* __restrict__ bf, const float* __restrict__ bi,
                              const float* __restrict__ bg, const float* __restrict__ bo)
{
    const int i = blockIdx.x * 256 + threadIdx.x;
    if (i < DIN_ * NG_) {
        const int k = i >> 12, n = i & 4095, gate = n >> 10, j = n & 1023;
        const float* W = (gate == 0) ? Wf : (gate == 1) ? Wi : (gate == 2) ? Wg : Wo;
        const float v = W[(size_t)k * DH_ + j];
        const __nv_bfloat16 h = __float2bfloat16(v);
        g_whx[i] = h;
        g_wlx[i] = __float2bfloat16(v - __bfloat162float(h));
    }
    if (i < NG_) {
        const int gate = i >> 10, j = i & 1023;
        const float* bb = (gate == 0) ? bf : (gate == 1) ? bi : (gate == 2) ? bg : bo;
        g_ball[i] = bb[j];
    }
}

__global__ void conv_x_kernel(const float* __restrict__ x)
{
    const int i = blockIdx.x * 256 + threadIdx.x;
    const int m = i >> 9, k = i & 511;
    const int b = m & 31, t = m >> 5;
    const float v = x[((size_t)b * S_ + t) * DIN_ + k];
    const __nv_bfloat16 h = __float2bfloat16(v);
    g_xhi[i] = h;
    g_xlo[i] = __float2bfloat16(v - __bfloat162float(h));
}

__global__ void conv_fc_kernel(const float* __restrict__ Wfc)
{
    const int i = blockIdx.x * 256 + threadIdx.x;
    const float v = Wfc[i];
    const __nv_bfloat16 h = __float2bfloat16(v);
    g_fchi[i] = h;
    g_fclo[i] = __float2bfloat16(v - __bfloat162float(h));
}

// ----------------------------------------------------------------
// Phase 1: gates_x = x @ Wx + bias via bf16-split mma. (R6, proven)
// ----------------------------------------------------------------
__global__ __launch_bounds__(256)
void gemm_gatesx_mma()
{
    const int n0 = blockIdx.x * 128;
    const int m0 = blockIdx.y * 128;

    __shared__ __align__(16) __nv_bfloat16 Ahi_s[128 * 40];
    __shared__ __align__(16) __nv_bfloat16 Alo_s[128 * 40];
    __shared__ __align__(16) __nv_bfloat16 Bhi_s[32 * 136];
    __shared__ __align__(16) __nv_bfloat16 Blo_s[32 * 136];

    const int tid = threadIdx.x, lane = tid & 31, warp = tid >> 5;
    const int wm = (warp >> 2) * 64, wn = (warp & 3) * 32;

    const int selA = lane >> 3;
    const int rowA = (selA & 1) * 8 + (lane & 7);
    const int kA   = (selA >> 1) * 8;
    const int qb   = lane >> 3;
    const int rowB = (qb & 1) * 8 + (lane & 7);
    const int nB   = (qb >> 1) * 8;

    const unsigned ahi_u = s2u(Ahi_s), alo_u = s2u(Alo_s);
    const unsigned bhi_u = s2u(Bhi_s), blo_u = s2u(Blo_s);

    float acc[4][4][4];
#pragma unroll
    for (int mf = 0; mf < 4; mf++)
#pragma unroll
        for (int nf = 0; nf < 4; nf++)
#pragma unroll
            for (int r = 0; r < 4; r++) acc[mf][nf][r] = 0.0f;

    for (int k0 = 0; k0 < DIN_; k0 += 32) {
        __syncthreads();
#pragma unroll
        for (int p = 0; p < 2; p++) {
            const int c  = tid + p * 256;
            const int m  = c >> 2, k8 = (c & 3) * 8;
            *reinterpret_cast<uint4*>(&Ahi_s[m * 40 + k8]) =
                *reinterpret_cast<const uint4*>(&g_xhi[(size_t)(m0 + m) * DIN_ + k0 + k8]);
            *reinterpret_cast<uint4*>(&Alo_s[m * 40 + k8]) =
                *reinterpret_cast<const uint4*>(&g_xlo[(size_t)(m0 + m) * DIN_ + k0 + k8]);
            const int kr = c >> 4, n8 = (c & 15) * 8;
            *reinterpret_cast<uint4*>(&Bhi_s[kr * 136 + n8]) =
                *reinterpret_cast<const uint4*>(&g_whx[(size_t)(k0 + kr) * NG_ + n0 + n8]);
            *reinterpret_cast<uint4*>(&Blo_s[kr * 136 + n8]) =
                *reinterpret_cast<const uint4*>(&g_wlx[(size_t)(k0 + kr) * NG_ + n0 + n8]);
        }
        __syncthreads();

#pragma unroll
        for (int ks = 0; ks < 2; ks++) {
            const int kb = ks * 16;
            unsigned ah[4][4], al[4][4];
#pragma unroll
            for (int mf = 0; mf < 4; mf++) {
                const unsigned off = (unsigned)((wm + mf * 16 + rowA) * 80 + (kb + kA) * 2);
                ldsm4(ah[mf][0], ah[mf][1], ah[mf][2], ah[mf][3], ahi_u + off);
                ldsm4(al[mf][0], al[mf][1], al[mf][2], al[mf][3], alo_u + off);
            }
            unsigned bh[4][2], bl[4][2];
#pragma unroll
            for (int np = 0; np < 2; np++) {
                const unsigned off = (unsigned)((kb + rowB) * 272 + (wn + np * 16 + nB) * 2);
                unsigned r0, r1, r2, r3;
                ldsm4t(r0, r1, r2, r3, bhi_u + off);
                bh[np * 2][0] = r0; bh[np * 2][1] = r1;
                bh[np * 2 + 1][0] = r2; bh[np * 2 + 1][1] = r3;
                ldsm4t(r0, r1, r2, r3, blo_u + off);
                bl[np * 2][0] = r0; bl[np * 2][1] = r1;
                bl[np * 2 + 1][0] = r2; bl[np * 2 + 1][1] = r3;
            }
#pragma unroll
            for (int mf = 0; mf < 4; mf++)
#pragma unroll
                for (int nf = 0; nf < 4; nf++) {
                    mma_bf16(acc[mf][nf][0], acc[mf][nf][1], acc[mf][nf][2], acc[mf][nf][3],
                             ah[mf][0], ah[mf][1], ah[mf][2], ah[mf][3],
                             bh[nf][0], bh[nf][1]);
                    mma_bf16(acc[mf][nf][0], acc[mf][nf][1], acc[mf][nf][2], acc[mf][nf][3],
                             ah[mf][0], ah[mf][1], ah[mf][2], ah[mf][3],
                             bl[nf][0], bl[nf][1]);
                    mma_bf16(acc[mf][nf][0], acc[mf][nf][1], acc[mf][nf][2], acc[mf][nf][3],
                             al[mf][0], al[mf][1], al[mf][2], al[mf][3],
                             bh[nf][0], bh[nf][1]);
                }
        }
    }

#pragma unroll
    for (int mf = 0; mf < 4; mf++) {
        const int r = m0 + wm + mf * 16 + (lane >> 2);
#pragma unroll
        for (int nf = 0; nf < 4; nf++) {
            const int c = n0 + wn + nf * 8 + (lane & 3) * 2;
            const float2 bv = *reinterpret_cast<const float2*>(&g_ball[c]);
            float2 v0, v1;
            v0.x = acc[mf][nf][0] + bv.x; v0.y = acc[mf][nf][1] + bv.y;
            v1.x = acc[mf][nf][2] + bv.x; v1.y = acc[mf][nf][3] + bv.y;
            *reinterpret_cast<float2*>(&g_gatesx[(size_t)r * NG_ + c]) = v0;
            *reinterpret_cast<float2*>(&g_gatesx[(size_t)(r + 8) * NG_ + c]) = v1;
        }
    }
}

// ----------------------------------------------------------------
// Phase 3: out = hs @ W_fc + b_fc via bf16-split mma. (R6, proven)
// ----------------------------------------------------------------
__global__ __launch_bounds__(256)
void gemm_fc_mma(const float* __restrict__ bfc, float* __restrict__ out)
{
    const int n0 = blockIdx.x * 128;
    const int m0 = blockIdx.y * 128;

    __shared__ __align__(16) __nv_bfloat16 Ahi_s[128 * 40];
    __shared__ __align__(16) __nv_bfloat16 Alo_s[128 * 40];
    __shared__ __align__(16) __nv_bfloat16 Bhi_s[32 * 136];
    __shared__ __align__(16) __nv_bfloat16 Blo_s[32 * 136];

    const int tid = threadIdx.x, lane = tid & 31, warp = tid >> 5;
    const int wm = (warp >> 2) * 64, wn = (warp & 3) * 32;

    const int selA = lane >> 3;
    const int rowA = (selA & 1) * 8 + (lane & 7);
    const int kA   = (selA >> 1) * 8;
    const int qb   = lane >> 3;
    const int rowB = (qb & 1) * 8 + (lane & 7);
    const int nB   = (qb >> 1) * 8;

    const unsigned ahi_u = s2u(Ahi_s), alo_u = s2u(Alo_s);
    const unsigned bhi_u = s2u(Bhi_s), blo_u = s2u(Blo_s);

    float acc[4][4][4];
#pragma unroll
    for (int mf = 0; mf < 4; mf++)
#pragma unroll
        for (int nf = 0; nf < 4; nf++)
#pragma unroll
            for (int r = 0; r < 4; r++) acc[mf][nf][r] = 0.0f;

    for (int k0 = 0; k0 < DH_; k0 += 32) {
        __syncthreads();
#pragma unroll
        for (int p = 0; p < 2; p++) {
            const int c  = tid + p * 256;
            const int m  = c >> 2, k8 = (c & 3) * 8;
            *reinterpret_cast<uint4*>(&Ahi_s[m * 40 + k8]) =
                *reinterpret_cast<const uint4*>(&g_hshi[(size_t)(m0 + m) * DH_ + k0 + k8]);
            *reinterpret_cast<uint4*>(&Alo_s[m * 40 + k8]) =
                *reinterpret_cast<const uint4*>(&g_hslo[(size_t)(m0 + m) * DH_ + k0 + k8]);
            const int kr = c >> 4, n8 = (c & 15) * 8;
            *reinterpret_cast<uint4*>(&Bhi_s[kr * 136 + n8]) =
                *reinterpret_cast<const uint4*>(&g_fchi[(size_t)(k0 + kr) * DOUT_ + n0 + n8]);
            *reinterpret_cast<uint4*>(&Blo_s[kr * 136 + n8]) =
                *reinterpret_cast<const uint4*>(&g_fclo[(size_t)(k0 + kr) * DOUT_ + n0 + n8]);
        }
        __syncthreads();

#pragma unroll
        for (int ks = 0; ks < 2; ks++) {
            const int kb = ks * 16;
            unsigned ah[4][4], al[4][4];
#pragma unroll
            for (int mf = 0; mf < 4; mf++) {
                const unsigned off = (unsigned)((wm + mf * 16 + rowA) * 80 + (kb + kA) * 2);
                ldsm4(ah[mf][0], ah[mf][1], ah[mf][2], ah[mf][3], ahi_u + off);
                ldsm4(al[mf][0], al[mf][1], al[mf][2], al[mf][3], alo_u + off);
            }
            unsigned bh[4][2], bl[4][2];
#pragma unroll
            for (int np = 0; np < 2; np++) {
                const unsigned off = (unsigned)((kb + rowB) * 272 + (wn + np * 16 + nB) * 2);
                unsigned r0, r1, r2, r3;
                ldsm4t(r0, r1, r2, r3, bhi_u + off);
                bh[np * 2][0] = r0; bh[np * 2][1] = r1;
                bh[np * 2 + 1][0] = r2; bh[np * 2 + 1][1] = r3;
                ldsm4t(r0, r1, r2, r3, blo_u + off);
                bl[np * 2][0] = r0; bl[np * 2][1] = r1;
                bl[np * 2 + 1][0] = r2; bl[np * 2 + 1][1] = r3;
            }
#pragma unroll
            for (int mf = 0; mf < 4; mf++)
#pragma unroll
                for (int nf = 0; nf < 4; nf++) {
                    mma_bf16(acc[mf][nf][0], acc[mf][nf][1], acc[mf][nf][2], acc[mf][nf][3],
                             ah[mf][0], ah[mf][1], ah[mf][2], ah[mf][3],
                             bh[nf][0], bh[nf][1]);
                    mma_bf16(acc[mf][nf][0], acc[mf][nf][1], acc[mf][nf][2], acc[mf][nf][3],
                             ah[mf][0], ah[mf][1], ah[mf][2], ah[mf][3],
                             bl[nf][0], bl[nf][1]);
                    mma_bf16(acc[mf][nf][0], acc[mf][nf][1], acc[mf][nf][2], acc[mf][nf][3],
                             al[mf][0], al[mf][1], al[mf][2], al[mf][3],
                             bh[nf][0], bh[nf][1]);
                }
        }
    }

#pragma unroll
    for (int mf = 0; mf < 4; mf++) {
        const int r = m0 + wm + mf * 16 + (lane >> 2);
#pragma unroll
        for (int nf = 0; nf < 4; nf++) {
            const int c = n0 + wn + nf * 8 + (lane & 3) * 2;
            const float2 bv = *reinterpret_cast<const float2*>(&bfc[c]);
            float2 v0, v1;
            v0.x = acc[mf][nf][0] + bv.x; v0.y = acc[mf][nf][1] + bv.y;
            v1.x = acc[mf][nf][2] + bv.x; v1.y = acc[mf][nf][3] + bv.y;
            {
                const int bb = r & 31, tt = r >> 5;
                *reinterpret_cast<float2*>(&out[((size_t)bb * S_ + tt) * DOUT_ + c]) = v0;
            }
            {
                const int r1i = r + 8;
                const int bb = r1i & 31, tt = r1i >> 5;
                *reinterpret_cast<float2*>(&out[((size_t)bb * S_ + tt) * DOUT_ + c]) = v1;
            }
        }
    }
}

// ----------------------------------------------------------------
// Phase 2: PERSISTENT recurrence — cp.async pipelined staging with
// FULL-CTA syncs (documented pattern), R6 atomic grid barrier.
// Commit group ch stages the ch-th 64-k sub-slice of EVERY quarter;
// mainloop = 4 sections: wait_group(3-sec) + __syncthreads + 4-kt mma.
// h read from g_hshi/g_hslo history (t-1); zero buffer for t=0.
// ----------------------------------------------------------------
__global__ __launch_bounds__(512, 1)
void lstm_persist_kernel(const float* __restrict__ Wf, const float* __restrict__ Wi,
                         const float* __restrict__ Wg, const float* __restrict__ Wo)
{
    extern __shared__ char smem[];
    char*  h_hi_s = smem;
    char*  h_lo_s = smem + HPLANE_B;
    float* zp     = reinterpret_cast<float*>(smem + ZP_OFF);
    float* c_s    = reinterpret_cast<float*>(smem + CS_OFF);

    const int tid  = threadIdx.x;
    const int lane = tid & 31;
    const int warp = tid >> 5;
    const int j0   = blockIdx.x * 8;

    const int kh   = warp >> 2;
    const int gate = warp & 3;
    const float* Wsel = (gate == 0) ? Wf : (gate == 1) ? Wi : (gate == 2) ? Wg : Wo;

    // ---- one-time: W fragments into registers ----
    const int jj = lane >> 2;
    const int kr = (lane & 3) * 2;
    unsigned wh[16][2], wl[16][2];
#pragma unroll
    for (int kt = 0; kt < 16; kt++) {
        const int kb = kh * 256 + kt * 16 + kr;
        const float w0a = Wsel[(size_t)(512 + kb + 0) * DH_ + j0 + jj];
        const float w0b = Wsel[(size_t)(512 + kb + 1) * DH_ + j0 + jj];
        const float w1a = Wsel[(size_t)(512 + kb + 8) * DH_ + j0 + jj];
        const float w1b = Wsel[(size_t)(512 + kb + 9) * DH_ + j0 + jj];
        split2(w0a, w0b, wh[kt][0], wl[kt][0]);
        split2(w1a, w1b, wh[kt][1], wl[kt][1]);
    }

    if (tid < 256) c_s[tid] = 0.0f;
    __syncthreads();

    // ldmatrix address components
    const int sel    = lane >> 3;
    const int rowoff = ((sel & 1) * 8) + (lane & 7);
    const int koff   = (sel >> 1) * 8;

    const unsigned hs_hi_u = s2u(h_hi_s);
    const unsigned hs_lo_u = s2u(h_lo_s);

    // staging mapping per commit: 2048 x 16B slots, 4 per thread
    // u = tid + p*512: plane = u>>10, v=u&1023: b=v>>5, w=v&31: khh=w>>3, o=w&7
    int stg_b[4], stg_kh[4], stg_o[4], stg_pl[4];
#pragma unroll
    for (int p = 0; p < 4; p++) {
        const int u = tid + p * 512;
        stg_pl[p] = u >> 10;
        const int v = u & 1023;
        stg_b[p]  = v >> 5;
        const int w = v & 31;
        stg_kh[p] = w >> 3;
        stg_o[p]  = w & 7;
    }

    // elementwise mapping (first 256 threads)
    const int b_e  = tid >> 3;
    const int jj_e = tid & 7;

    volatile unsigned* barp = &g_bar;

    for (int t = 0; t < S_; ++t) {
        const __nv_bfloat16* __restrict__ hhi_in =
            (t == 0) ? g_h0hi : (g_hshi + (size_t)(t - 1) * B_ * DH_);
        const __nv_bfloat16* __restrict__ hlo_in =
            (t == 0) ? g_h0lo : (g_hslo + (size_t)(t - 1) * B_ * DH_);
        const float* __restrict__ gx_t = g_gatesx + (size_t)t * B_ * NG_;

        float gxv[4];
        if (tid < 256) {
#pragma unroll
            for (int g = 0; g < 4; g++)
                gxv[g] = __ldg(&gx_t[(size_t)b_e * NG_ + g * DH_ + j0 + jj_e]);
        }

        // ---- issue 4 staging commits; commit ch = 64-k sub-slice of each quarter
#pragma unroll
        for (int ch = 0; ch < 4; ch++) {
#pragma unroll
            for (int p = 0; p < 4; p++) {
                const int b = stg_b[p], khh = stg_kh[p], o = stg_o[p];
                const int kbase = khh * 256 + ch * 64;
                const size_t src_e = (size_t)b * DH_ + kbase + o * 8;
                const unsigned dst = (unsigned)(b * ROWB + kbase * 2 + o * 16);
                if (stg_pl[p] == 0) cpasync16(hs_hi_u + dst, hhi_in + src_e);
                else                cpasync16(hs_lo_u + dst, hlo_in + src_e);
            }
            cp_commit();
        }

        // ---- mma mainloop: 4 sections of 4 kt ----
        float acc[2][4];
#pragma unroll
        for (int mt = 0; mt < 2; mt++)
#pragma unroll
            for (int r = 0; r < 4; r++) acc[mt][r] = 0.0f;

#pragma unroll
        for (int sec = 0; sec < 4; sec++) {
            if      (sec == 0) cp_wait<3>();
            else if (sec == 1) cp_wait<2>();
            else if (sec == 2) cp_wait<1>();
            else               cp_wait<0>();
            __syncthreads();

#pragma unroll
            for (int k2 = 0; k2 < 4; k2++) {
                const int kt = sec * 4 + k2;
                const int kbase = kh * 256 + kt * 16;
                unsigned ah[2][4], al[2][4];
#pragma unroll
                for (int mt = 0; mt < 2; mt++) {
                    const unsigned byte = (unsigned)((mt * 16 + rowoff) * ROWB
                                         + (kbase + koff) * 2);
                    ldsm4(ah[mt][0], ah[mt][1], ah[mt][2], ah[mt][3], hs_hi_u + byte);
                    ldsm4(al[mt][0], al[mt][1], al[mt][2], al[mt][3], hs_lo_u + byte);
                }
#pragma unroll
                for (int mt = 0; mt < 2; mt++) {
                    mma_bf16(acc[mt][0], acc[mt][1], acc[mt][2], acc[mt][3],
                             ah[mt][0], ah[mt][1], ah[mt][2], ah[mt][3],
                             wh[kt][0], wh[kt][1]);
                    mma_bf16(acc[mt][0], acc[mt][1], acc[mt][2], acc[mt][3],
                             ah[mt][0], ah[mt][1], ah[mt][2], ah[mt][3],
                             wl[kt][0], wl[kt][1]);
                    mma_bf16(acc[mt][0], acc[mt][1], acc[mt][2], acc[mt][3],
                             al[mt][0], al[mt][1], al[mt][2], al[mt][3],
                             wh[kt][0], wh[kt][1]);
                }
            }
        }

        // ---- write partials: zp[kh][b][c] ----
        {
            const int g  = lane >> 2;
            const int cp = (lane & 3) * 2;
#pragma unroll
            for (int mt = 0; mt < 2; mt++) {
                const int b0 = mt * 16 + g;
                float2 v01 = make_float2(acc[mt][0], acc[mt][1]);
                float2 v23 = make_float2(acc[mt][2], acc[mt][3]);
                *reinterpret_cast<float2*>(
                    &zp[(kh * 32 + b0) * ZP_STRIDE + gate * 8 + cp]) = v01;
                *reinterpret_cast<float2*>(
                    &zp[(kh * 32 + b0 + 8) * ZP_STRIDE + gate * 8 + cp]) = v23;
            }
        }
        __syncthreads();

        // ---- elementwise LSTM (threads < 256) ----
        if (tid < 256) {
            float z[4];
#pragma unroll
            for (int g = 0; g < 4; g++) {
                float s = gxv[g];
#pragma unroll
                for (int q = 0; q < 4; q++)
                    s += zp[(q * 32 + b_e) * ZP_STRIDE + g * 8 + jj_e];
                z[g] = s;
            }
            const float fg = sigf(z[0]);
            const float ig = sigf(z[1]);
            const float gg = tanhfast(z[2]);
            const float og = sigf(z[3]);

            const float cn = fg * c_s[tid] + ig * gg;
            c_s[tid] = cn;
            const float hn = og * tanhfast(cn);

            const int gj = j0 + jj_e;
            const size_t hidx = (size_t)t * B_ * DH_ + (size_t)b_e * DH_ + gj;
            const __nv_bfloat16 hh = __float2bfloat16(hn);
            g_hshi[hidx] = hh;
            g_hslo[hidx] = __float2bfloat16(hn - __bfloat162float(hh));
        }

        // ---- grid barrier (R6 proven atomic version) ----
        __syncthreads();
        if (t < S_ - 1) {
            if (tid == 0) {
                __threadfence();
                atomicAdd((unsigned*)&g_bar, 1u);
                const unsigned target = (unsigned)(NCTA_ * (t + 1));
                while (*barp < target) { }
                __threadfence();
            }
            __syncthreads();
        }
    }
}

// ----------------------------------------------------------------
extern "C" void kernel_launch(void* const* d_in, const int* in_sizes, int n_in,
                              void* d_out, int out_size)
{
    const float* x   = (const float*)d_in[0];
    const float* Wf  = (const float*)d_in[1];
    const float* bf  = (const float*)d_in[2];
    const float* Wi  = (const float*)d_in[3];
    const float* bi  = (const float*)d_in[4];
    const float* Wg  = (const float*)d_in[5];
    const float* bg  = (const float*)d_in[6];
    const float* Wo  = (const float*)d_in[7];
    const float* bo  = (const float*)d_in[8];
    const float* Wfc = (const float*)d_in[9];
    const float* bfc = (const float*)d_in[10];
    float* out = (float*)d_out;

    static bool configured = false;
    if (!configured) {
        cudaFuncSetAttribute(lstm_persist_kernel,
                             cudaFuncAttributeMaxDynamicSharedMemorySize, SMEM_P_BYTES);
        configured = true;
    }

    init_state_kernel<<<(B_ * DH_ + 255) / 256, 256>>>();

    conv_w_kernel<<<(DIN_ * NG_ + 255) / 256, 256>>>(Wf, Wi, Wg, Wo, bf, bi, bg, bo);
    conv_x_kernel<<<(M_ * DIN_ + 255) / 256, 256>>>(x);
    conv_fc_kernel<<<(DH_ * DOUT_ + 255) / 256, 256>>>(Wfc);

    {
        dim3 grid(NG_ / 128, M_ / 128);
        gemm_gatesx_mma<<<grid, 256>>>();
    }

    lstm_persist_kernel<<<NCTA_, 512, SMEM_P_BYTES>>>(Wf, Wi, Wg, Wo);

    {
        dim3 grid(DOUT_ / 128, M_ / 128);
        gemm_fc_mma<<<grid, 256>>>(bfc, out);
    }
}